// round 9
// baseline (speedup 1.0000x reference)
#include <cuda_runtime.h>
#include <math_constants.h>

#define IMG_H 64
#define IMG_W 2048
#define KNN_CUTOFF 1.0f
#define P_CAP 131072
#define OVF_CAP 32768

#define PTS_PER_BLK 64
#define THREADS_FUSED (PTS_PER_BLK * 5)   // 320

// inv_g[k] = 1 - gauss(k)/sum(gauss), sigma=1, 5x5, row-major (ky,kx)
__device__ __constant__ float INV_G_C[25] = {
    0.99703098f, 0.98669378f, 0.97806177f, 0.98669378f, 0.99703098f,
    0.98669378f, 0.94036569f, 0.90167956f, 0.94036569f, 0.98669378f,
    0.97806177f, 0.90167956f, 0.83789717f, 0.90167956f, 0.97806177f,
    0.98669378f, 0.94036569f, 0.90167956f, 0.94036569f, 0.98669378f,
    0.99703098f, 0.98669378f, 0.97806177f, 0.98669378f, 0.99703098f
};

__device__ __forceinline__ constexpr float inv_g_k(int k) {
    constexpr float g[25] = {
        0.99703098f, 0.98669378f, 0.97806177f, 0.98669378f, 0.99703098f,
        0.98669378f, 0.94036569f, 0.90167956f, 0.94036569f, 0.98669378f,
        0.97806177f, 0.90167956f, 0.83789717f, 0.90167956f, 0.97806177f,
        0.98669378f, 0.94036569f, 0.90167956f, 0.94036569f, 0.98669378f,
        0.99703098f, 0.98669378f, 0.97806177f, 0.98669378f, 0.99703098f
    };
    return g[k];
}

__device__ int g_ovf_count;    // zero-initialized at load; fixup resets after use
__device__ int g_ovf[OVF_CAP];

// ---------------------------------------------------------------------------
// Fused kernel: 5 threads/point. Phase 1 (role = row): build cutoff mask.
// Phase 2 (role = channel chunk): gather probs for mask winners, store.
// Overflow points (>5 cutoff passers, ~5e-4) get provisional output here and
// are enqueued for exact recompute in knn_fixup.
// ---------------------------------------------------------------------------
__global__ __launch_bounds__(THREADS_FUSED)
void knn_fused(const float*  __restrict__ proj_range,
               const float*  __restrict__ unproj,
               const float4* __restrict__ probs4,    // [H*W][5] float4
               const int*    __restrict__ px,
               const int*    __restrict__ py,
               float4*       __restrict__ out4,      // [P][5] float4
               int P)
{
    __shared__ unsigned smAll[THREADS_FUSED];  // 25-bit partial cutoff masks
    __shared__ unsigned smIB [THREADS_FUSED];  // 25-bit partial contributor masks

    const int tid = threadIdx.x;
    const int g   = tid / 5;                   // local point
    const int r   = tid - g * 5;               // role: row / channel chunk
    const int p   = blockIdx.x * PTS_PER_BLK + g;
    const bool active = (p < P);

    int x0 = 0, y0 = 0;
    float ur = 0.0f;

    // ---------------- phase 1: this thread's window row ----------------
    unsigned partAll = 0, partIB = 0;
    if (active) {
        x0 = px[p];
        y0 = py[p];
        ur = unproj[p];

        const int yy  = y0 + r - 2;
        const bool rv = ((unsigned)yy < (unsigned)IMG_H);
        const int yyc = rv ? yy : 0;

        if (x0 >= 2 && x0 <= IMG_W - 3) {
            const int xb   = x0 - 2;
            const int base = xb & ~3;          // aligned; W%4==0 so in-range
            const bool b1  = (xb & 2) != 0;
            const bool b0  = (xb & 1) != 0;
            const float4* rp = (const float4*)(proj_range + yyc * IMG_W + base);
            const float4 lo = __ldg(rp);
            const float4 hi = __ldg(rp + 1);
            const float h0 = b1 ? lo.z : lo.x;
            const float h1 = b1 ? lo.w : lo.y;
            const float h2 = b1 ? hi.x : lo.z;
            const float h3 = b1 ? hi.y : lo.w;
            const float h4 = b1 ? hi.z : hi.x;
            const float h5 = b1 ? hi.w : hi.y;
            float wv[5];
            wv[0] = b0 ? h1 : h0;
            wv[1] = b0 ? h2 : h1;
            wv[2] = b0 ? h3 : h2;
            wv[3] = b0 ? h4 : h3;
            wv[4] = b0 ? h5 : h4;
#pragma unroll
            for (int i = 0; i < 5; ++i) {
                const int k = r * 5 + i;
                const float rr = rv ? wv[i] : 0.0f;   // OOB row = unfold zero-pad
                const float d  = fabsf(rr - ur) * INV_G_C[k];
                const bool pass = (d <= KNN_CUTOFF) && (rr >= 0.0f);
                if (pass)       partAll |= (1u << k);
                if (pass && rv) partIB  |= (1u << k);
            }
        } else {
            // edge columns (~0.25%): scalar clamped loads for this row
#pragma unroll
            for (int i = 0; i < 5; ++i) {
                const int k  = r * 5 + i;
                const int xx = x0 + i - 2;
                const bool valid = rv && ((unsigned)xx < (unsigned)IMG_W);
                const int xxc = valid ? xx : 0;
                const float rawr = __ldg(proj_range + yyc * IMG_W + xxc);
                const float rr = valid ? rawr : 0.0f;
                const float d  = fabsf(rr - ur) * INV_G_C[k];
                const bool pass = (d <= KNN_CUTOFF) && (rr >= 0.0f);
                if (pass)          partAll |= (1u << k);
                if (pass && valid) partIB  |= (1u << k);
            }
        }
    }
    smAll[tid] = partAll;
    smIB [tid] = partIB;

    __syncthreads();

    if (!active) return;

    // ---------------- combine (each thread, redundantly; no 2nd sync) ---
    const int gb = g * 5;
    unsigned maskAll = smAll[gb] | smAll[gb+1] | smAll[gb+2] | smAll[gb+3] | smAll[gb+4];
    unsigned maskIB  = smIB [gb] | smIB [gb+1] | smIB [gb+2] | smIB [gb+3] | smIB [gb+4];
    maskAll |= (1u << 12);   // center: d forced 0, always passes, in-bounds
    maskIB  |= (1u << 12);

    if (r == 0 && __popc(maskAll) > 5) {
        const int slot = atomicAdd(&g_ovf_count, 1);
        if (slot < OVF_CAP) g_ovf[slot] = p;   // fixup overwrites out4[p]
    }

    // ---------------- phase 2: gather channel chunk r --------------------
    const int base = y0 * IMG_W + x0;

    int kk[5];
    {
        unsigned mm = maskIB;
#pragma unroll
        for (int i = 0; i < 5; ++i) {
            kk[i] = __ffs(mm) - 1;             // -1 when exhausted
            mm &= mm - 1;
        }
    }

    float4 v[5];
#pragma unroll
    for (int i = 0; i < 5; ++i) {
        const int k  = kk[i];
        const int ky = (k * 205) >> 10;        // k/5 for k in [0,24]
        const int idx = base + k + ky * 2043 - 4098;  // = base+(ky-2)*W+(kx-2)
        if (k >= 0) v[i] = __ldg(probs4 + (size_t)idx * 5 + r);
    }

    float4 acc = make_float4(0.f, 0.f, 0.f, 0.f);
#pragma unroll
    for (int i = 0; i < 5; ++i) {
        if (kk[i] >= 0) {
            acc.x += v[i].x; acc.y += v[i].y;
            acc.z += v[i].z; acc.w += v[i].w;
        }
    }

    out4[(size_t)p * 5 + r] = acc;             // fully coalesced
}

// ---------------------------------------------------------------------------
// Fixup: exact top-5 + full output recompute for overflow points (~70).
// SINGLE BLOCK. Resets the overflow counter after consuming it.
// ---------------------------------------------------------------------------
__global__ __launch_bounds__(128)
void knn_fixup(const float*  __restrict__ proj_range,
               const float*  __restrict__ unproj,
               const float4* __restrict__ probs4,
               const int*    __restrict__ px,
               const int*    __restrict__ py,
               float4*       __restrict__ out4)
{
    int n = g_ovf_count;
    if (n > OVF_CAP) n = OVF_CAP;

    for (int i = threadIdx.x; i < n; i += blockDim.x) {
        const int p  = g_ovf[i];
        const int x0 = px[p];
        const int y0 = py[p];
        const float ur = unproj[p];

        unsigned key[25];
        unsigned ib = 0;
#pragma unroll
        for (int k = 0; k < 25; ++k) {
            const int yy = y0 + (k / 5) - 2;
            const int xx = x0 + (k % 5) - 2;
            const bool valid = ((unsigned)yy < (unsigned)IMG_H) &&
                               ((unsigned)xx < (unsigned)IMG_W);
            const int yyc = valid ? yy : 0;
            const int xxc = valid ? xx : 0;
            float rr = valid ? __ldg(proj_range + yyc * IMG_W + xxc) : 0.0f;
            if (rr < 0.0f) rr = CUDART_INF_F;
            if (k == 12)   rr = ur;
            key[k] = __float_as_uint(fabsf(rr - ur) * INV_G_C[k]);
            if (valid) ib |= (1u << k);
        }

        unsigned nm = 0;
#pragma unroll
        for (int sel = 0; sel < 5; ++sel) {
            unsigned v[32];
#pragma unroll
            for (int k = 0; k < 25; ++k) v[k] = key[k];
#pragma unroll
            for (int k = 25; k < 32; ++k) v[k] = 0xFFFFFFFFu;
#pragma unroll
            for (int s = 16; s >= 1; s >>= 1)
#pragma unroll
                for (int j = 0; j < s; ++j) v[j] = min(v[j], v[j + s]);
            const unsigned m = v[0];

            unsigned ix[32];
#pragma unroll
            for (int k = 0; k < 25; ++k) ix[k] = (key[k] == m) ? (unsigned)k : 32u;
#pragma unroll
            for (int k = 25; k < 32; ++k) ix[k] = 32u;
#pragma unroll
            for (int s = 16; s >= 1; s >>= 1)
#pragma unroll
                for (int j = 0; j < s; ++j) ix[j] = min(ix[j], ix[j + s]);
            const unsigned bi = ix[0];

            nm |= (1u << bi);                 // winners all have d <= cutoff here
#pragma unroll
            for (int k = 0; k < 25; ++k)
                if ((unsigned)k == bi) key[k] = 0xFFFFFFFFu;
        }

        // recompute the 5 output chunks for this point
        unsigned m = nm & ib;
        const int base = y0 * IMG_W + x0;
        float4 a0 = make_float4(0.f,0.f,0.f,0.f), a1 = a0, a2 = a0, a3 = a0, a4 = a0;
        while (m) {
            const int k  = __ffs(m) - 1;
            m &= m - 1;
            const int ky = (k * 205) >> 10;
            const int idx = base + k + ky * 2043 - 4098;
            const float4* row = probs4 + (size_t)idx * 5;
            float4 t;
            t = __ldg(row + 0); a0.x += t.x; a0.y += t.y; a0.z += t.z; a0.w += t.w;
            t = __ldg(row + 1); a1.x += t.x; a1.y += t.y; a1.z += t.z; a1.w += t.w;
            t = __ldg(row + 2); a2.x += t.x; a2.y += t.y; a2.z += t.z; a2.w += t.w;
            t = __ldg(row + 3); a3.x += t.x; a3.y += t.y; a3.z += t.z; a3.w += t.w;
            t = __ldg(row + 4); a4.x += t.x; a4.y += t.y; a4.z += t.z; a4.w += t.w;
        }
        float4* o = out4 + (size_t)p * 5;
        o[0] = a0; o[1] = a1; o[2] = a2; o[3] = a3; o[4] = a4;
    }

    __syncthreads();
    if (threadIdx.x == 0) g_ovf_count = 0;    // ready for next graph replay
}

extern "C" void kernel_launch(void* const* d_in, const int* in_sizes, int n_in,
                              void* d_out, int out_size)
{
    const float*  proj_range = (const float*)  d_in[0];
    const float*  unproj     = (const float*)  d_in[1];
    const float4* probs4     = (const float4*) d_in[2];
    const int*    px         = (const int*)    d_in[3];
    const int*    py         = (const int*)    d_in[4];
    float4*       out4       = (float4*)       d_out;

    int P = in_sizes[1];                 // unproj_range element count
    if (P > P_CAP) P = P_CAP;            // scratch capacity guard (fixed-shape problem)

    const int blocks = (P + PTS_PER_BLK - 1) / PTS_PER_BLK;
    knn_fused<<<blocks, THREADS_FUSED>>>(proj_range, unproj, probs4,
                                         px, py, out4, P);
    knn_fixup<<<1, 128>>>(proj_range, unproj, probs4, px, py, out4);
}

// round 10
// speedup vs baseline: 1.1697x; 1.1697x over previous
#include <cuda_runtime.h>
#include <math_constants.h>

#define IMG_H 64
#define IMG_W 2048
#define KNN_CUTOFF 1.0f
#define P_CAP 131072
#define OVF_CAP 32768

#define PTS_PER_BLK 64
#define THREADS_FUSED (PTS_PER_BLK * 5)   // 320

#define FIX_BLOCKS 148
#define FIX_THREADS 64

// inv_g[k] = 1 - gauss(k)/sum(gauss), sigma=1, 5x5, row-major (ky,kx)
__device__ __constant__ float INV_G_C[25] = {
    0.99703098f, 0.98669378f, 0.97806177f, 0.98669378f, 0.99703098f,
    0.98669378f, 0.94036569f, 0.90167956f, 0.94036569f, 0.98669378f,
    0.97806177f, 0.90167956f, 0.83789717f, 0.90167956f, 0.97806177f,
    0.98669378f, 0.94036569f, 0.90167956f, 0.94036569f, 0.98669378f,
    0.99703098f, 0.98669378f, 0.97806177f, 0.98669378f, 0.99703098f
};

__device__ int g_ovf_count;    // zero at load; reset by last fixup block
__device__ int g_done;         // fixup completion counter
__device__ int g_ovf[OVF_CAP];

// ---------------------------------------------------------------------------
// Fused kernel: 5 threads/point. Phase 1 (role = row): build cutoff mask.
// Phase 2 (role = channel chunk): gather probs for mask winners, store.
// Overflow points (>5 cutoff passers, ~5e-4) get provisional output here and
// are enqueued for exact recompute in knn_fixup.
// ---------------------------------------------------------------------------
__global__ __launch_bounds__(THREADS_FUSED)
void knn_fused(const float*  __restrict__ proj_range,
               const float*  __restrict__ unproj,
               const float4* __restrict__ probs4,    // [H*W][5] float4
               const int*    __restrict__ px,
               const int*    __restrict__ py,
               float4*       __restrict__ out4,      // [P][5] float4
               int P)
{
    __shared__ unsigned smAll[THREADS_FUSED];  // 25-bit partial cutoff masks
    __shared__ unsigned smIB [THREADS_FUSED];  // 25-bit partial contributor masks

    const int tid = threadIdx.x;
    const int g   = tid / 5;                   // local point
    const int r   = tid - g * 5;               // role: row / channel chunk
    const int p   = blockIdx.x * PTS_PER_BLK + g;
    const bool active = (p < P);

    int x0 = 0, y0 = 0;
    float ur = 0.0f;

    // ---------------- phase 1: this thread's window row ----------------
    unsigned partAll = 0, partIB = 0;
    if (active) {
        x0 = px[p];
        y0 = py[p];
        ur = unproj[p];

        const int yy  = y0 + r - 2;
        const bool rv = ((unsigned)yy < (unsigned)IMG_H);
        const int yyc = rv ? yy : 0;

        if (x0 >= 2 && x0 <= IMG_W - 3) {
            const int xb   = x0 - 2;
            const int base = xb & ~3;          // aligned; W%4==0 so in-range
            const bool b1  = (xb & 2) != 0;
            const bool b0  = (xb & 1) != 0;
            const float4* rp = (const float4*)(proj_range + yyc * IMG_W + base);
            const float4 lo = __ldg(rp);
            const float4 hi = __ldg(rp + 1);
            const float h0 = b1 ? lo.z : lo.x;
            const float h1 = b1 ? lo.w : lo.y;
            const float h2 = b1 ? hi.x : lo.z;
            const float h3 = b1 ? hi.y : lo.w;
            const float h4 = b1 ? hi.z : hi.x;
            const float h5 = b1 ? hi.w : hi.y;
            float wv[5];
            wv[0] = b0 ? h1 : h0;
            wv[1] = b0 ? h2 : h1;
            wv[2] = b0 ? h3 : h2;
            wv[3] = b0 ? h4 : h3;
            wv[4] = b0 ? h5 : h4;
#pragma unroll
            for (int i = 0; i < 5; ++i) {
                const int k = r * 5 + i;
                const float rr = rv ? wv[i] : 0.0f;   // OOB row = unfold zero-pad
                const float d  = fabsf(rr - ur) * INV_G_C[k];
                const bool pass = (d <= KNN_CUTOFF) && (rr >= 0.0f);
                if (pass)       partAll |= (1u << k);
                if (pass && rv) partIB  |= (1u << k);
            }
        } else {
            // edge columns (~0.25%): scalar clamped loads for this row
#pragma unroll
            for (int i = 0; i < 5; ++i) {
                const int k  = r * 5 + i;
                const int xx = x0 + i - 2;
                const bool valid = rv && ((unsigned)xx < (unsigned)IMG_W);
                const int xxc = valid ? xx : 0;
                const float rawr = __ldg(proj_range + yyc * IMG_W + xxc);
                const float rr = valid ? rawr : 0.0f;
                const float d  = fabsf(rr - ur) * INV_G_C[k];
                const bool pass = (d <= KNN_CUTOFF) && (rr >= 0.0f);
                if (pass)          partAll |= (1u << k);
                if (pass && valid) partIB  |= (1u << k);
            }
        }
    }
    smAll[tid] = partAll;
    smIB [tid] = partIB;

    __syncthreads();

    if (!active) return;

    // ---------------- combine (each thread, redundantly; no 2nd sync) ---
    const int gb = g * 5;
    unsigned maskAll = smAll[gb] | smAll[gb+1] | smAll[gb+2] | smAll[gb+3] | smAll[gb+4];
    unsigned maskIB  = smIB [gb] | smIB [gb+1] | smIB [gb+2] | smIB [gb+3] | smIB [gb+4];
    maskAll |= (1u << 12);   // center: d forced 0, always passes, in-bounds
    maskIB  |= (1u << 12);

    if (r == 0 && __popc(maskAll) > 5) {
        const int slot = atomicAdd(&g_ovf_count, 1);
        if (slot < OVF_CAP) g_ovf[slot] = p;   // fixup overwrites out4[p]
    }

    // ---------------- phase 2: gather channel chunk r --------------------
    const int base = y0 * IMG_W + x0;

    int kk[5];
    {
        unsigned mm = maskIB;
#pragma unroll
        for (int i = 0; i < 5; ++i) {
            kk[i] = __ffs(mm) - 1;             // -1 when exhausted
            mm &= mm - 1;
        }
    }

    float4 v[5];
#pragma unroll
    for (int i = 0; i < 5; ++i) {
        const int k  = kk[i];
        const int ky = (k * 205) >> 10;        // k/5 for k in [0,24]
        const int idx = base + k + ky * 2043 - 4098;  // = base+(ky-2)*W+(kx-2)
        if (k >= 0) v[i] = __ldg(probs4 + (size_t)idx * 5 + r);
    }

    float4 acc = make_float4(0.f, 0.f, 0.f, 0.f);
#pragma unroll
    for (int i = 0; i < 5; ++i) {
        if (kk[i] >= 0) {
            acc.x += v[i].x; acc.y += v[i].y;
            acc.z += v[i].z; acc.w += v[i].w;
        }
    }

    out4[(size_t)p * 5 + r] = acc;             // fully coalesced
}

// ---------------------------------------------------------------------------
// Fixup: exact top-5 + full output recompute for overflow points (~70).
// Many blocks (latency hiding); linear u64 (key,idx) argmin — NO scratch
// arrays, no spills. Last block to finish resets the counters.
// ---------------------------------------------------------------------------
__global__ __launch_bounds__(FIX_THREADS)
void knn_fixup(const float*  __restrict__ proj_range,
               const float*  __restrict__ unproj,
               const float4* __restrict__ probs4,
               const int*    __restrict__ px,
               const int*    __restrict__ py,
               float4*       __restrict__ out4)
{
    int n = g_ovf_count;
    if (n > OVF_CAP) n = OVF_CAP;

    for (int i = blockIdx.x * blockDim.x + threadIdx.x; i < n;
         i += gridDim.x * blockDim.x) {
        const int p  = g_ovf[i];
        const int x0 = px[p];
        const int y0 = py[p];
        const float ur = unproj[p];

        unsigned key[25];
        unsigned ib = 0;
#pragma unroll
        for (int k = 0; k < 25; ++k) {
            const int yy = y0 + (k / 5) - 2;
            const int xx = x0 + (k % 5) - 2;
            const bool valid = ((unsigned)yy < (unsigned)IMG_H) &&
                               ((unsigned)xx < (unsigned)IMG_W);
            const int yyc = valid ? yy : 0;
            const int xxc = valid ? xx : 0;
            float rr = valid ? __ldg(proj_range + yyc * IMG_W + xxc) : 0.0f;
            if (rr < 0.0f) rr = CUDART_INF_F;
            if (k == 12)   rr = ur;
            key[k] = __float_as_uint(fabsf(rr - ur) * INV_G_C[k]);
            if (valid) ib |= (1u << k);
        }

        // 5 rounds of linear (key,idx) argmin: ascending value, lowest idx ties
        unsigned nm = 0;
#pragma unroll
        for (int sel = 0; sel < 5; ++sel) {
            unsigned long long best = ~0ull;
#pragma unroll
            for (int k = 0; k < 25; ++k) {
                const unsigned long long c =
                    ((unsigned long long)key[k] << 32) | (unsigned)k;
                if (c < best) best = c;
            }
            const unsigned bi = (unsigned)(best & 0xFFFFFFFFu);
            nm |= (1u << bi);                 // winners all have d <= cutoff here
#pragma unroll
            for (int k = 0; k < 25; ++k)
                if ((unsigned)k == bi) key[k] = 0xFFFFFFFFu;
        }

        // recompute the 5 output chunks for this point
        unsigned m = nm & ib;
        const int base = y0 * IMG_W + x0;
        float4 a0 = make_float4(0.f,0.f,0.f,0.f), a1 = a0, a2 = a0, a3 = a0, a4 = a0;
        while (m) {
            const int k  = __ffs(m) - 1;
            m &= m - 1;
            const int ky = (k * 205) >> 10;
            const int idx = base + k + ky * 2043 - 4098;
            const float4* row = probs4 + (size_t)idx * 5;
            float4 t;
            t = __ldg(row + 0); a0.x += t.x; a0.y += t.y; a0.z += t.z; a0.w += t.w;
            t = __ldg(row + 1); a1.x += t.x; a1.y += t.y; a1.z += t.z; a1.w += t.w;
            t = __ldg(row + 2); a2.x += t.x; a2.y += t.y; a2.z += t.z; a2.w += t.w;
            t = __ldg(row + 3); a3.x += t.x; a3.y += t.y; a3.z += t.z; a3.w += t.w;
            t = __ldg(row + 4); a4.x += t.x; a4.y += t.y; a4.z += t.z; a4.w += t.w;
        }
        float4* o = out4 + (size_t)p * 5;
        o[0] = a0; o[1] = a1; o[2] = a2; o[3] = a3; o[4] = a4;
    }

    // last block to finish resets counters for the next graph replay
    __shared__ bool last;
    __threadfence();
    __syncthreads();
    if (threadIdx.x == 0) {
        const int done = atomicAdd(&g_done, 1);
        last = (done == (int)gridDim.x - 1);
    }
    __syncthreads();
    if (last && threadIdx.x == 0) {
        g_ovf_count = 0;
        g_done = 0;
    }
}

extern "C" void kernel_launch(void* const* d_in, const int* in_sizes, int n_in,
                              void* d_out, int out_size)
{
    const float*  proj_range = (const float*)  d_in[0];
    const float*  unproj     = (const float*)  d_in[1];
    const float4* probs4     = (const float4*) d_in[2];
    const int*    px         = (const int*)    d_in[3];
    const int*    py         = (const int*)    d_in[4];
    float4*       out4       = (float4*)       d_out;

    int P = in_sizes[1];                 // unproj_range element count
    if (P > P_CAP) P = P_CAP;            // scratch capacity guard (fixed-shape problem)

    const int blocks = (P + PTS_PER_BLK - 1) / PTS_PER_BLK;
    knn_fused<<<blocks, THREADS_FUSED>>>(proj_range, unproj, probs4,
                                         px, py, out4, P);
    knn_fixup<<<FIX_BLOCKS, FIX_THREADS>>>(proj_range, unproj, probs4,
                                           px, py, out4);
}

// round 11
// speedup vs baseline: 1.7364x; 1.4845x over previous
#include <cuda_runtime.h>
#include <math_constants.h>

#define IMG_H 64
#define IMG_W 2048
#define KNN_CUTOFF 1.0f

#define PTS_PER_BLK 64
#define THREADS_FUSED (PTS_PER_BLK * 5)   // 320

// inv_g[k] = 1 - gauss(k)/sum(gauss), sigma=1, 5x5, row-major (ky,kx)
__device__ __constant__ float INV_G_C[25] = {
    0.99703098f, 0.98669378f, 0.97806177f, 0.98669378f, 0.99703098f,
    0.98669378f, 0.94036569f, 0.90167956f, 0.94036569f, 0.98669378f,
    0.97806177f, 0.90167956f, 0.83789717f, 0.90167956f, 0.97806177f,
    0.98669378f, 0.94036569f, 0.90167956f, 0.94036569f, 0.98669378f,
    0.99703098f, 0.98669378f, 0.97806177f, 0.98669378f, 0.99703098f
};

// ---------------------------------------------------------------------------
// COLD path (~65 of 131072 points): exact top-5 with reference tie-breaking.
// __noinline__ so its registers don't pollute the hot path. Straight-line
// u64 (key,idx) argmin — no scratch arrays, no spills, no dynamic loops.
// Returns the corrected contributor mask (top-5 winners that are in-bounds).
// ---------------------------------------------------------------------------
__device__ __noinline__
unsigned knn_exact_top5(const float* __restrict__ proj_range,
                        int x0, int y0, float ur)
{
    unsigned key[25];
    unsigned ib = 0;
#pragma unroll
    for (int k = 0; k < 25; ++k) {
        const int yy = y0 + (k / 5) - 2;
        const int xx = x0 + (k % 5) - 2;
        const bool valid = ((unsigned)yy < (unsigned)IMG_H) &&
                           ((unsigned)xx < (unsigned)IMG_W);
        const int yyc = valid ? yy : 0;
        const int xxc = valid ? xx : 0;
        float rr = valid ? __ldg(proj_range + yyc * IMG_W + xxc) : 0.0f;
        if (rr < 0.0f) rr = CUDART_INF_F;   // matches reference
        if (k == 12)   rr = ur;             // center: d = 0
        key[k] = __float_as_uint(fabsf(rr - ur) * INV_G_C[k]);
        if (valid) ib |= (1u << k);
    }

    unsigned nm = 0;
#pragma unroll
    for (int sel = 0; sel < 5; ++sel) {
        unsigned long long best = ~0ull;
#pragma unroll
        for (int k = 0; k < 25; ++k) {
            const unsigned long long c =
                ((unsigned long long)key[k] << 32) | (unsigned)k;
            if (c < best) best = c;
        }
        const unsigned bi = (unsigned)(best & 0xFFFFFFFFu);
        nm |= (1u << bi);     // all 5 winners have d <= cutoff (>5 passers exist)
#pragma unroll
        for (int k = 0; k < 25; ++k)
            if ((unsigned)k == bi) key[k] = 0xFFFFFFFFu;
    }

    return nm & ib;           // OOB winners contribute zero probs: drop
}

// ---------------------------------------------------------------------------
// Fused kernel: 5 threads/point.
// Phase 1 (role = window row): build cutoff mask cooperatively via smem.
// Phase 2 (role = channel chunk): gather probs for mask winners, store.
// Rare overflow (>5 cutoff passers, ~5e-4): inline cold-path exact top-5.
// ---------------------------------------------------------------------------
__global__ __launch_bounds__(THREADS_FUSED)
void knn_fused(const float*  __restrict__ proj_range,
               const float*  __restrict__ unproj,
               const float4* __restrict__ probs4,    // [H*W][5] float4
               const int*    __restrict__ px,
               const int*    __restrict__ py,
               float4*       __restrict__ out4,      // [P][5] float4
               int P)
{
    __shared__ unsigned smAll[THREADS_FUSED];  // 25-bit partial cutoff masks
    __shared__ unsigned smIB [THREADS_FUSED];  // 25-bit partial contributor masks

    const int tid = threadIdx.x;
    const int g   = tid / 5;                   // local point
    const int r   = tid - g * 5;               // role: row / channel chunk
    const int p   = blockIdx.x * PTS_PER_BLK + g;
    const bool active = (p < P);

    int x0 = 0, y0 = 0;
    float ur = 0.0f;

    // ---------------- phase 1: this thread's window row ----------------
    unsigned partAll = 0, partIB = 0;
    if (active) {
        x0 = px[p];
        y0 = py[p];
        ur = unproj[p];

        const int yy  = y0 + r - 2;
        const bool rv = ((unsigned)yy < (unsigned)IMG_H);
        const int yyc = rv ? yy : 0;

        if (x0 >= 2 && x0 <= IMG_W - 3) {
            const int xb   = x0 - 2;
            const int base = xb & ~3;          // aligned; W%4==0 so in-range
            const bool b1  = (xb & 2) != 0;
            const bool b0  = (xb & 1) != 0;
            const float4* rp = (const float4*)(proj_range + yyc * IMG_W + base);
            const float4 lo = __ldg(rp);
            const float4 hi = __ldg(rp + 1);
            const float h0 = b1 ? lo.z : lo.x;
            const float h1 = b1 ? lo.w : lo.y;
            const float h2 = b1 ? hi.x : lo.z;
            const float h3 = b1 ? hi.y : lo.w;
            const float h4 = b1 ? hi.z : hi.x;
            const float h5 = b1 ? hi.w : hi.y;
            float wv[5];
            wv[0] = b0 ? h1 : h0;
            wv[1] = b0 ? h2 : h1;
            wv[2] = b0 ? h3 : h2;
            wv[3] = b0 ? h4 : h3;
            wv[4] = b0 ? h5 : h4;
#pragma unroll
            for (int i = 0; i < 5; ++i) {
                const int k = r * 5 + i;
                const float rr = rv ? wv[i] : 0.0f;   // OOB row = unfold zero-pad
                const float d  = fabsf(rr - ur) * INV_G_C[k];
                const bool pass = (d <= KNN_CUTOFF) && (rr >= 0.0f);
                if (pass)       partAll |= (1u << k);
                if (pass && rv) partIB  |= (1u << k);
            }
        } else {
            // edge columns (~0.25%): scalar clamped loads for this row
#pragma unroll
            for (int i = 0; i < 5; ++i) {
                const int k  = r * 5 + i;
                const int xx = x0 + i - 2;
                const bool valid = rv && ((unsigned)xx < (unsigned)IMG_W);
                const int xxc = valid ? xx : 0;
                const float rawr = __ldg(proj_range + yyc * IMG_W + xxc);
                const float rr = valid ? rawr : 0.0f;
                const float d  = fabsf(rr - ur) * INV_G_C[k];
                const bool pass = (d <= KNN_CUTOFF) && (rr >= 0.0f);
                if (pass)          partAll |= (1u << k);
                if (pass && valid) partIB  |= (1u << k);
            }
        }
    }
    smAll[tid] = partAll;
    smIB [tid] = partIB;

    __syncthreads();

    if (!active) return;

    // ---------------- combine (each thread, redundantly; no 2nd sync) ---
    const int gb = g * 5;
    unsigned maskAll = smAll[gb] | smAll[gb+1] | smAll[gb+2] | smAll[gb+3] | smAll[gb+4];
    unsigned maskIB  = smIB [gb] | smIB [gb+1] | smIB [gb+2] | smIB [gb+3] | smIB [gb+4];
    maskAll |= (1u << 12);   // center: d forced 0, always passes, in-bounds
    maskIB  |= (1u << 12);

    // rare overflow: all 5 threads of this point recompute exactly (cold fn)
    if (__popc(maskAll) > 5) {
        maskIB = knn_exact_top5(proj_range, x0, y0, ur);
    }

    // ---------------- phase 2: gather channel chunk r --------------------
    const int base = y0 * IMG_W + x0;

    int kk[5];
    {
        unsigned mm = maskIB;
#pragma unroll
        for (int i = 0; i < 5; ++i) {
            kk[i] = __ffs(mm) - 1;             // -1 when exhausted
            mm &= mm - 1;
        }
    }

    float4 v[5];
#pragma unroll
    for (int i = 0; i < 5; ++i) {
        const int k  = kk[i];
        const int ky = (k * 205) >> 10;        // k/5 for k in [0,24]
        const int idx = base + k + ky * 2043 - 4098;  // = base+(ky-2)*W+(kx-2)
        if (k >= 0) v[i] = __ldg(probs4 + (size_t)idx * 5 + r);
    }

    float4 acc = make_float4(0.f, 0.f, 0.f, 0.f);
#pragma unroll
    for (int i = 0; i < 5; ++i) {
        if (kk[i] >= 0) {
            acc.x += v[i].x; acc.y += v[i].y;
            acc.z += v[i].z; acc.w += v[i].w;
        }
    }

    out4[(size_t)p * 5 + r] = acc;             // fully coalesced
}

extern "C" void kernel_launch(void* const* d_in, const int* in_sizes, int n_in,
                              void* d_out, int out_size)
{
    const float*  proj_range = (const float*)  d_in[0];
    const float*  unproj     = (const float*)  d_in[1];
    const float4* probs4     = (const float4*) d_in[2];
    const int*    px         = (const int*)    d_in[3];
    const int*    py         = (const int*)    d_in[4];
    float4*       out4       = (float4*)       d_out;

    const int P = in_sizes[1];           // unproj_range element count
    const int blocks = (P + PTS_PER_BLK - 1) / PTS_PER_BLK;
    knn_fused<<<blocks, THREADS_FUSED>>>(proj_range, unproj, probs4,
                                         px, py, out4, P);
}